// round 1
// baseline (speedup 1.0000x reference)
#include <cuda_runtime.h>
#include <math.h>

// Problem constants: B=2, S=2048 -> T=4096 tokens, H=1024, E=8, K=2, FF=4096
#define TT   4096
#define HH   1024
#define EE   8
#define KK   2
#define FFD  4096
#define RTOT (TT*KK)   // total routed rows: every token picks exactly 2 experts -> 8192
#define LN_EPS 1e-5f

// ---------------------------------------------------------------------------
// Scratch (static device allocations; kernel_launch itself allocates nothing)
// ---------------------------------------------------------------------------
__device__ float g_xhat[TT * HH];                    // 16 MB : (x-mu)*rsig
__device__ float g_h[RTOT * HH];                     // 32 MB : per-row LN-affine input
__device__ float g_act[(long long)RTOT * FFD];       // 134 MB: gelu(h@W1+b1)
__device__ float g_y[RTOT * HH];                     // 32 MB : act@W2 (raw)
__device__ int   g_cnt[EE];
__device__ int   g_off[EE + 1];
__device__ int   g_slot_e[RTOT];                     // per (token,k)
__device__ int   g_slot_pos[RTOT];
__device__ int   g_slot_row[RTOT];
__device__ float g_slot_w[RTOT];
__device__ int   g_row_tok[RTOT];                    // per compact row
__device__ int   g_row_e[RTOT];

// ---------------------------------------------------------------------------
// Kernel 0: zero expert counters
// ---------------------------------------------------------------------------
__global__ void k_zero() {
    if (threadIdx.x < EE) g_cnt[threadIdx.x] = 0;
}

// ---------------------------------------------------------------------------
// Kernel 1: per-token router logits + top-2 softmax + LayerNorm stats + xhat
// One block (256 threads) per token.
// ---------------------------------------------------------------------------
__global__ void __launch_bounds__(256) k_router_ln(
    const float* __restrict__ x,
    const float* __restrict__ rW,    // [H,E] row-major
    const float* __restrict__ rb)    // [E]
{
    __shared__ float xs[HH];
    __shared__ float rs[8], rs2[8];
    __shared__ float lg[EE];
    __shared__ float s_mu, s_rs;

    const int t   = blockIdx.x;
    const int tid = threadIdx.x;
    const int wid = tid >> 5, lane = tid & 31;
    const float* xr = x + (long long)t * HH;

    float s = 0.f, s2 = 0.f;
    for (int c = tid; c < HH; c += 256) {
        float v = xr[c];
        xs[c] = v;
        s += v; s2 += v * v;
    }
    // block reduce
    #pragma unroll
    for (int o = 16; o; o >>= 1) {
        s  += __shfl_down_sync(0xFFFFFFFFu, s,  o);
        s2 += __shfl_down_sync(0xFFFFFFFFu, s2, o);
    }
    if (lane == 0) { rs[wid] = s; rs2[wid] = s2; }
    __syncthreads();
    if (tid == 0) {
        float S = 0.f, S2 = 0.f;
        #pragma unroll
        for (int i = 0; i < 8; i++) { S += rs[i]; S2 += rs2[i]; }
        float mu  = S / (float)HH;
        float var = S2 / (float)HH - mu * mu;
        s_mu = mu;
        s_rs = rsqrtf(var + LN_EPS);
    }
    __syncthreads();
    const float mu = s_mu, rsg = s_rs;
    for (int c = tid; c < HH; c += 256)
        g_xhat[t * HH + c] = (xs[c] - mu) * rsg;

    // logits: warp w computes expert w's dot(x, rW[:,w])
    float p = 0.f;
    for (int c = lane; c < HH; c += 32)
        p += xs[c] * rW[c * EE + wid];
    #pragma unroll
    for (int o = 16; o; o >>= 1) p += __shfl_down_sync(0xFFFFFFFFu, p, o);
    if (lane == 0) lg[wid] = p + rb[wid];
    __syncthreads();

    if (tid == 0) {
        // top-2 (strict > keeps lowest index on ties, matching lax.top_k)
        int e0 = 0;
        #pragma unroll
        for (int e = 1; e < EE; e++) if (lg[e] > lg[e0]) e0 = e;
        int e1 = (e0 == 0) ? 1 : 0;
        #pragma unroll
        for (int e = 0; e < EE; e++) {
            if (e == e0) continue;
            if (lg[e] > lg[e1]) e1 = e;
        }
        float p1 = expf(lg[e1] - lg[e0]);     // <= 1
        float inv = 1.f / (1.f + p1);
        float w0 = inv, w1 = p1 * inv;

        int   es[2] = { e0, e1 };
        float ws[2] = { w0, w1 };
        #pragma unroll
        for (int k = 0; k < 2; k++) {
            int e   = es[k];
            int pos = atomicAdd(&g_cnt[e], 1);
            g_slot_e[t * 2 + k]   = e;
            g_slot_pos[t * 2 + k] = pos;
            g_slot_w[t * 2 + k]   = ws[k];
        }
    }
}

// ---------------------------------------------------------------------------
// Kernel 2: exclusive prefix over 8 counters
// ---------------------------------------------------------------------------
__global__ void k_prefix() {
    if (threadIdx.x == 0) {
        int a = 0;
        #pragma unroll
        for (int e = 0; e < EE; e++) { g_off[e] = a; a += g_cnt[e]; }
        g_off[EE] = a;   // == RTOT always
    }
}

// ---------------------------------------------------------------------------
// Kernel 3: slot -> compact row mapping
// ---------------------------------------------------------------------------
__global__ void k_build() {
    int i = blockIdx.x * blockDim.x + threadIdx.x;
    if (i >= RTOT) return;
    int e   = g_slot_e[i];
    int row = g_off[e] + g_slot_pos[i];
    g_slot_row[i] = row;
    g_row_tok[row] = i >> 1;
    g_row_e[row]   = e;
}

// ---------------------------------------------------------------------------
// Kernel 4: materialize h[row] = xhat[tok] * ln_g[e] + ln_b[e]
// ---------------------------------------------------------------------------
__global__ void __launch_bounds__(256) k_build_h(
    const float* __restrict__ lng, const float* __restrict__ lnb)
{
    const int row = blockIdx.x;
    const int tok = g_row_tok[row];
    const int e   = g_row_e[row];
    const float* xh = g_xhat + (long long)tok * HH;
    const float* gg = lng + (long long)e * HH;
    const float* bb = lnb + (long long)e * HH;
    float* o = g_h + (long long)row * HH;
    for (int c = threadIdx.x; c < HH; c += 256)
        o[c] = fmaf(xh[c], gg[c], bb[c]);
}

// ---------------------------------------------------------------------------
// Grouped SGEMM: per expert segment [g_off[e], g_off[e+1]) of rows.
// FIRST=true : A=g_h  [rows x 1024], B=W1[e] [1024 x 4096], C=g_act, +b1, GELU
// FIRST=false: A=g_act[rows x 4096], B=W2[e] [4096 x 1024], C=g_y (raw)
// 128x128 tile, BK=8, 256 threads, 8x8 microtile.
// ---------------------------------------------------------------------------
template <bool FIRST>
__global__ void __launch_bounds__(256) k_gemm(
    const float* __restrict__ Wmat,   // [E, Kdim, N]
    const float* __restrict__ bias)   // [E, N] (only FIRST)
{
    constexpr int BM = 128, BN = 128, BK = 8;
    constexpr int KD = FIRST ? HH : FFD;
    constexpr int ND = FIRST ? FFD : HH;

    const int e    = blockIdx.z;
    const int r0   = g_off[e];
    const int rows = g_off[e + 1] - r0;
    const int row0 = blockIdx.y * BM;
    if (row0 >= rows) return;
    const int n0 = blockIdx.x * BN;

    const float* A  = FIRST ? g_h : g_act;
    float*       C  = FIRST ? g_act : g_y;
    const float* Bp = Wmat + (long long)e * KD * ND;

    __shared__ float As[BK][BM];
    __shared__ float Bs[BK][BN];

    const int tid = threadIdx.x;
    const int tx = tid & 15, ty = tid >> 4;

    float acc[8][8];
    #pragma unroll
    for (int i = 0; i < 8; i++)
        #pragma unroll
        for (int j = 0; j < 8; j++) acc[i][j] = 0.f;

    // A tile loaders: 128 rows x 8 k, 4 floats/thread
    const int aRow = tid >> 1;
    const int aC   = (tid & 1) * 4;
    const bool m_ok = (row0 + aRow) < rows;
    const float* Arow = A + (long long)(r0 + row0 + aRow) * KD;
    // B tile loaders: 8 k x 128 n, float4/thread
    const int bK = tid >> 5;
    const int bN = (tid & 31) * 4;

    for (int k0 = 0; k0 < KD; k0 += BK) {
        float4 av = m_ok ? *(const float4*)(Arow + k0 + aC)
                         : make_float4(0.f, 0.f, 0.f, 0.f);
        As[aC + 0][aRow] = av.x;
        As[aC + 1][aRow] = av.y;
        As[aC + 2][aRow] = av.z;
        As[aC + 3][aRow] = av.w;
        float4 bv = *(const float4*)(Bp + (long long)(k0 + bK) * ND + n0 + bN);
        *(float4*)&Bs[bK][bN] = bv;
        __syncthreads();

        #pragma unroll
        for (int k = 0; k < BK; k++) {
            float ra[8], rb[8];
            #pragma unroll
            for (int i = 0; i < 8; i++) ra[i] = As[k][ty * 8 + i];
            #pragma unroll
            for (int j = 0; j < 8; j++) rb[j] = Bs[k][tx * 8 + j];
            #pragma unroll
            for (int i = 0; i < 8; i++)
                #pragma unroll
                for (int j = 0; j < 8; j++)
                    acc[i][j] = fmaf(ra[i], rb[j], acc[i][j]);
        }
        __syncthreads();
    }

    // epilogue
    #pragma unroll
    for (int i = 0; i < 8; i++) {
        int m = row0 + ty * 8 + i;
        if (m >= rows) break;
        float* Crow = C + (long long)(r0 + m) * ND + n0 + tx * 8;
        #pragma unroll
        for (int j = 0; j < 8; j++) {
            float v = acc[i][j];
            if (FIRST) {
                v += bias[(long long)e * ND + n0 + tx * 8 + j];
                v = 0.5f * v * (1.0f + erff(v * 0.70710678118654752f)); // exact gelu
            }
            Crow[j] = v;
        }
    }
}

// ---------------------------------------------------------------------------
// Kernel 7: combine  out = x + w0*(y0 + b2[e0]) + w1*(y1 + b2[e1])
// (residual factored out since softmax gates sum to 1; no float atomics ->
//  bitwise-deterministic output independent of atomic row ordering)
// ---------------------------------------------------------------------------
__global__ void __launch_bounds__(256) k_combine(
    const float* __restrict__ x,
    const float* __restrict__ b2,
    float* __restrict__ out)
{
    const int t = blockIdx.x;
    const int r0 = g_slot_row[t * 2 + 0], r1 = g_slot_row[t * 2 + 1];
    const int e0 = g_slot_e[t * 2 + 0],  e1 = g_slot_e[t * 2 + 1];
    const float w0 = g_slot_w[t * 2 + 0], w1 = g_slot_w[t * 2 + 1];
    const float* y0 = g_y + (long long)r0 * HH;
    const float* y1 = g_y + (long long)r1 * HH;
    const float* bb0 = b2 + (long long)e0 * HH;
    const float* bb1 = b2 + (long long)e1 * HH;
    const float* xr = x + (long long)t * HH;
    float* o = out + (long long)t * HH;
    for (int c = threadIdx.x; c < HH; c += 256)
        o[c] = xr[c] + w0 * (y0[c] + bb0[c]) + w1 * (y1[c] + bb1[c]);
}

// ---------------------------------------------------------------------------
// Launch
// ---------------------------------------------------------------------------
extern "C" void kernel_launch(void* const* d_in, const int* in_sizes, int n_in,
                              void* d_out, int out_size)
{
    const float* x   = (const float*)d_in[0];
    const float* rW  = (const float*)d_in[1];
    const float* rb  = (const float*)d_in[2];
    const float* lng = (const float*)d_in[3];
    const float* lnb = (const float*)d_in[4];
    const float* W1  = (const float*)d_in[5];
    const float* b1  = (const float*)d_in[6];
    const float* W2  = (const float*)d_in[7];
    const float* b2  = (const float*)d_in[8];
    float* out = (float*)d_out;

    k_zero<<<1, 32>>>();
    k_router_ln<<<TT, 256>>>(x, rW, rb);
    k_prefix<<<1, 32>>>();
    k_build<<<RTOT / 256, 256>>>();
    k_build_h<<<RTOT, 256>>>(lng, lnb);

    dim3 g1(FFD / 128, TT / 128, EE);   // 32 x 32 x 8, most exit early
    k_gemm<true><<<g1, 256>>>(W1, b1);

    dim3 g2(HH / 128, TT / 128, EE);    // 8 x 32 x 8
    k_gemm<false><<<g2, 256>>>(W2, nullptr);

    k_combine<<<TT, 256>>>(x, b2, out);
}

// round 3
// speedup vs baseline: 1.5404x; 1.5404x over previous
#include <cuda_runtime.h>
#include <math.h>
#include <stdint.h>
#include <mma.h>

using namespace nvcuda;

// Problem constants: B=2, S=2048 -> T=4096 tokens, H=1024, E=8, K=2, FF=4096
#define TT   4096
#define HH   1024
#define EE   8
#define FFD  4096
#define RTOT (TT*2)
#define LN_EPS 1e-5f

// ---------------------------------------------------------------------------
// Scratch
// ---------------------------------------------------------------------------
__device__ float g_xhat[TT * HH];
__device__ float g_h[RTOT * HH];
__device__ float g_act[(long long)RTOT * FFD];
__device__ float g_y[RTOT * HH];
__device__ int   g_cnt[EE];
__device__ int   g_off[EE + 1];
__device__ int   g_slot_e[RTOT];
__device__ int   g_slot_pos[RTOT];
__device__ int   g_slot_row[RTOT];
__device__ float g_slot_w[RTOT];
__device__ int   g_row_tok[RTOT];
__device__ int   g_row_e[RTOT];

// ---------------------------------------------------------------------------
// Helpers
// ---------------------------------------------------------------------------
__device__ __forceinline__ uint32_t smem_u32(const void* p) {
    uint32_t a;
    asm("{ .reg .u64 t; cvta.to.shared.u64 t, %1; cvt.u32.u64 %0, t; }" : "=r"(a) : "l"(p));
    return a;
}
#define CP16(dst, src) \
    asm volatile("cp.async.cg.shared.global [%0], [%1], 16;" :: "r"(dst), "l"(src))
#define CP_COMMIT() asm volatile("cp.async.commit_group;" ::: "memory")
#define CP_WAIT0()  asm volatile("cp.async.wait_group 0;" ::: "memory")
#define CP_WAIT1()  asm volatile("cp.async.wait_group 1;" ::: "memory")

// ---------------------------------------------------------------------------
// Kernel 0-4: router / LN / compaction
// ---------------------------------------------------------------------------
__global__ void k_zero() { if (threadIdx.x < EE) g_cnt[threadIdx.x] = 0; }

__global__ void __launch_bounds__(256) k_router_ln(
    const float* __restrict__ x, const float* __restrict__ rW, const float* __restrict__ rb)
{
    __shared__ float xs[HH];
    __shared__ float rs[8], rs2[8];
    __shared__ float lg[EE];
    __shared__ float s_mu, s_rs;

    const int t = blockIdx.x, tid = threadIdx.x;
    const int wid = tid >> 5, lane = tid & 31;
    const float* xr = x + (long long)t * HH;

    float s = 0.f, s2 = 0.f;
    for (int c = tid; c < HH; c += 256) { float v = xr[c]; xs[c] = v; s += v; s2 += v * v; }
    #pragma unroll
    for (int o = 16; o; o >>= 1) {
        s  += __shfl_down_sync(0xFFFFFFFFu, s, o);
        s2 += __shfl_down_sync(0xFFFFFFFFu, s2, o);
    }
    if (lane == 0) { rs[wid] = s; rs2[wid] = s2; }
    __syncthreads();
    if (tid == 0) {
        float S = 0.f, S2 = 0.f;
        #pragma unroll
        for (int i = 0; i < 8; i++) { S += rs[i]; S2 += rs2[i]; }
        float mu = S / (float)HH;
        s_mu = mu; s_rs = rsqrtf(S2 / (float)HH - mu * mu + LN_EPS);
    }
    __syncthreads();
    const float mu = s_mu, rsg = s_rs;
    for (int c = tid; c < HH; c += 256) g_xhat[t * HH + c] = (xs[c] - mu) * rsg;

    float p = 0.f;
    for (int c = lane; c < HH; c += 32) p += xs[c] * rW[c * EE + wid];
    #pragma unroll
    for (int o = 16; o; o >>= 1) p += __shfl_down_sync(0xFFFFFFFFu, p, o);
    if (lane == 0) lg[wid] = p + rb[wid];
    __syncthreads();

    if (tid == 0) {
        int e0 = 0;
        #pragma unroll
        for (int e = 1; e < EE; e++) if (lg[e] > lg[e0]) e0 = e;
        int e1 = (e0 == 0) ? 1 : 0;
        #pragma unroll
        for (int e = 0; e < EE; e++) { if (e == e0) continue; if (lg[e] > lg[e1]) e1 = e; }
        float p1 = expf(lg[e1] - lg[e0]);
        float inv = 1.f / (1.f + p1);
        int   es[2] = { e0, e1 };
        float ws[2] = { inv, p1 * inv };
        #pragma unroll
        for (int k = 0; k < 2; k++) {
            int e = es[k];
            int pos = atomicAdd(&g_cnt[e], 1);
            g_slot_e[t * 2 + k] = e; g_slot_pos[t * 2 + k] = pos; g_slot_w[t * 2 + k] = ws[k];
        }
    }
}

__global__ void k_prefix() {
    if (threadIdx.x == 0) {
        int a = 0;
        #pragma unroll
        for (int e = 0; e < EE; e++) { g_off[e] = a; a += g_cnt[e]; }
        g_off[EE] = a;
    }
}

__global__ void k_build() {
    int i = blockIdx.x * blockDim.x + threadIdx.x;
    if (i >= RTOT) return;
    int e = g_slot_e[i];
    int row = g_off[e] + g_slot_pos[i];
    g_slot_row[i] = row;
    g_row_tok[row] = i >> 1;
    g_row_e[row] = e;
}

__global__ void __launch_bounds__(256) k_build_h(
    const float* __restrict__ lng, const float* __restrict__ lnb)
{
    const int row = blockIdx.x;
    const int tok = g_row_tok[row];
    const int e = g_row_e[row];
    const float* xh = g_xhat + (long long)tok * HH;
    const float* gg = lng + (long long)e * HH;
    const float* bb = lnb + (long long)e * HH;
    float* o = g_h + (long long)row * HH;
    for (int c = threadIdx.x; c < HH; c += 256) o[c] = fmaf(xh[c], gg[c], bb[c]);
}

// ---------------------------------------------------------------------------
// tf32 wmma grouped GEMM: BM=128, BN=128, BK=32, 256 threads (8 warps, 4x2),
// warp tile 32x64 (2x4 m16n16k8 acc frags), cp.async double-buffered.
// FIRST: A=g_h[rows,1024] B=W1[e][1024,4096] -> gelu(.+b1) -> g_act
// else : A=g_act[rows,4096] B=W2[e][4096,1024] -> g_y raw
// ---------------------------------------------------------------------------
// SMEM float layout: A0[128*40] A1[128*40] B0[32*136] B1[32*136]  (75776 B)
#define A_LDM 40
#define B_LDM 136
#define A_STF (128 * A_LDM)     // 5120 floats / stage
#define B_STF (32 * B_LDM)      // 4352 floats / stage
#define GEMM_SMEM_BYTES ((2 * A_STF + 2 * B_STF) * 4)
#define OUT_LDM 132

template <bool FIRST>
__global__ void __launch_bounds__(256) k_gemm_mma(
    const float* __restrict__ Wmat, const float* __restrict__ bias)
{
    constexpr int KD  = FIRST ? HH : FFD;
    constexpr int ND  = FIRST ? FFD : HH;
    constexpr int NIT = KD / 32;

    const int e    = blockIdx.z;
    const int r0   = g_off[e];
    const int rows = g_off[e + 1] - r0;
    const int row0 = blockIdx.y * 128;
    if (row0 >= rows) return;
    const int n0 = blockIdx.x * 128;

    extern __shared__ float sm[];
    const uint32_t sbase = smem_u32(sm);

    const int tid  = threadIdx.x;
    const int w    = tid >> 5;
    const int wm   = w >> 1;        // 0..3 -> rows wm*32
    const int wn   = w & 1;         // 0..1 -> cols wn*64

    const float* A  = FIRST ? g_h : g_act;
    float*       C  = FIRST ? g_act : g_y;
    const float* Bg = Wmat + (size_t)e * KD * ND;

    wmma::fragment<wmma::accumulator, 16, 16, 8, float> acc[2][4];
    #pragma unroll
    for (int i = 0; i < 2; i++)
        #pragma unroll
        for (int j = 0; j < 4; j++) wmma::fill_fragment(acc[i][j], 0.f);

    // precompute loader indices
    const int arL = tid >> 3;              // 0..31 : A row within pass
    const int akc = (tid & 7) * 4;         // A k-chunk
    const int bkL = tid >> 6;              // 0..3  : B k within pass
    const int bnc = (tid & 63) * 2;        // hmm -- recompute below properly

    auto load_stage = [&](int it, int buf) {
        const int k0 = it * 32;
        // A: 128 rows x 32 floats = 1024 x 16B chunks, 4 per thread
        #pragma unroll
        for (int j = 0; j < 4; j++) {
            int idx = tid + 256 * j;
            int r = idx >> 3, kc = (idx & 7) * 4;
            int arow = row0 + r; if (arow >= rows) arow = rows - 1;
            const float* src = A + (size_t)(r0 + arow) * KD + k0 + kc;
            uint32_t dst = sbase + (uint32_t)(buf * A_STF + r * A_LDM + kc) * 4u;
            CP16(dst, src);
        }
        // B: 32 k x 128 n = 1024 x 16B chunks, 4 per thread
        #pragma unroll
        for (int j = 0; j < 4; j++) {
            int idx = tid + 256 * j;
            int kk = idx >> 5, nc = (idx & 31) * 4;
            const float* src = Bg + (size_t)(k0 + kk) * ND + n0 + nc;
            uint32_t dst = sbase + (uint32_t)(2 * A_STF + buf * B_STF + kk * B_LDM + nc) * 4u;
            CP16(dst, src);
        }
        CP_COMMIT();
    };

    load_stage(0, 0);

    for (int it = 0; it < NIT; ++it) {
        if (it + 1 < NIT) { load_stage(it + 1, (it + 1) & 1); CP_WAIT1(); }
        else              { CP_WAIT0(); }
        __syncthreads();

        const float* pA = sm + (it & 1) * A_STF;
        const float* pB = sm + 2 * A_STF + (it & 1) * B_STF;

        #pragma unroll
        for (int ks = 0; ks < 4; ks++) {
            wmma::fragment<wmma::matrix_a, 16, 16, 8, wmma::precision::tf32, wmma::row_major> af[2];
            wmma::fragment<wmma::matrix_b, 16, 16, 8, wmma::precision::tf32, wmma::row_major> bf[4];
            #pragma unroll
            for (int i = 0; i < 2; i++) {
                wmma::load_matrix_sync(af[i], pA + (wm * 32 + i * 16) * A_LDM + ks * 8, A_LDM);
                #pragma unroll
                for (int q = 0; q < af[i].num_elements; q++)
                    af[i].x[q] = wmma::__float_to_tf32(af[i].x[q]);
            }
            #pragma unroll
            for (int j = 0; j < 4; j++) {
                wmma::load_matrix_sync(bf[j], pB + (ks * 8) * B_LDM + wn * 64 + j * 16, B_LDM);
                #pragma unroll
                for (int q = 0; q < bf[j].num_elements; q++)
                    bf[j].x[q] = wmma::__float_to_tf32(bf[j].x[q]);
            }
            #pragma unroll
            for (int i = 0; i < 2; i++)
                #pragma unroll
                for (int j = 0; j < 4; j++)
                    wmma::mma_sync(acc[i][j], af[i], bf[j], acc[i][j]);
        }
        __syncthreads();
    }

    // Epilogue via smem (guarded stores; partial tiles must not spill into
    // the next expert's rows). Reuse the pipeline smem: 128 x 132 floats.
    #pragma unroll
    for (int i = 0; i < 2; i++)
        #pragma unroll
        for (int j = 0; j < 4; j++)
            wmma::store_matrix_sync(
                sm + (size_t)(wm * 32 + i * 16) * OUT_LDM + wn * 64 + j * 16,
                acc[i][j], OUT_LDM, wmma::mem_row_major);
    __syncthreads();

    const int col = (tid & 31) * 4;
    const float* brow = FIRST ? (bias + (size_t)e * ND + n0) : (const float*)0;
    #pragma unroll
    for (int rr = 0; rr < 16; rr++) {
        int r = (tid >> 5) + rr * 8;
        int m = row0 + r;
        if (m < rows) {
            const float* so = sm + (size_t)r * OUT_LDM + col;
            float v0 = so[0], v1 = so[1], v2 = so[2], v3 = so[3];
            if (FIRST) {
                float4 bv = *(const float4*)(brow + col);
                v0 += bv.x; v1 += bv.y; v2 += bv.z; v3 += bv.w;
                v0 = 0.5f * v0 * (1.0f + erff(v0 * 0.70710678118654752f));
                v1 = 0.5f * v1 * (1.0f + erff(v1 * 0.70710678118654752f));
                v2 = 0.5f * v2 * (1.0f + erff(v2 * 0.70710678118654752f));
                v3 = 0.5f * v3 * (1.0f + erff(v3 * 0.70710678118654752f));
            }
            *(float4*)(C + (size_t)(r0 + m) * ND + n0 + col) = make_float4(v0, v1, v2, v3);
        }
    }
}

// ---------------------------------------------------------------------------
// Combine
// ---------------------------------------------------------------------------
__global__ void __launch_bounds__(256) k_combine(
    const float* __restrict__ x, const float* __restrict__ b2, float* __restrict__ out)
{
    const int t = blockIdx.x;
    const int r0 = g_slot_row[t * 2 + 0], r1 = g_slot_row[t * 2 + 1];
    const int e0 = g_slot_e[t * 2 + 0],  e1 = g_slot_e[t * 2 + 1];
    const float w0 = g_slot_w[t * 2 + 0], w1 = g_slot_w[t * 2 + 1];
    const float* y0 = g_y + (long long)r0 * HH;
    const float* y1 = g_y + (long long)r1 * HH;
    const float* bb0 = b2 + (long long)e0 * HH;
    const float* bb1 = b2 + (long long)e1 * HH;
    const float* xr = x + (long long)t * HH;
    float* o = out + (long long)t * HH;
    for (int c = threadIdx.x; c < HH; c += 256)
        o[c] = xr[c] + w0 * (y0[c] + bb0[c]) + w1 * (y1[c] + bb1[c]);
}

// ---------------------------------------------------------------------------
// Launch
// ---------------------------------------------------------------------------
extern "C" void kernel_launch(void* const* d_in, const int* in_sizes, int n_in,
                              void* d_out, int out_size)
{
    const float* x   = (const float*)d_in[0];
    const float* rW  = (const float*)d_in[1];
    const float* rb  = (const float*)d_in[2];
    const float* lng = (const float*)d_in[3];
    const float* lnb = (const float*)d_in[4];
    const float* W1  = (const float*)d_in[5];
    const float* b1  = (const float*)d_in[6];
    const float* W2  = (const float*)d_in[7];
    const float* b2  = (const float*)d_in[8];
    float* out = (float*)d_out;

    // Unconditional (deterministic, host-side, not a stream op).
    cudaFuncSetAttribute(k_gemm_mma<true>,  cudaFuncAttributeMaxDynamicSharedMemorySize, GEMM_SMEM_BYTES);
    cudaFuncSetAttribute(k_gemm_mma<false>, cudaFuncAttributeMaxDynamicSharedMemorySize, GEMM_SMEM_BYTES);

    k_zero<<<1, 32>>>();
    k_router_ln<<<TT, 256>>>(x, rW, rb);
    k_prefix<<<1, 32>>>();
    k_build<<<RTOT / 256, 256>>>();
    k_build_h<<<RTOT, 256>>>(lng, lnb);

    dim3 g1(FFD / 128, RTOT / 128, EE);   // 32 x 64 x 8 (most m-tiles exit early)
    k_gemm_mma<true><<<g1, 256, GEMM_SMEM_BYTES>>>(W1, b1);

    dim3 g2(HH / 128, RTOT / 128, EE);    // 8 x 64 x 8
    k_gemm_mma<false><<<g2, 256, GEMM_SMEM_BYTES>>>(W2, nullptr);

    k_combine<<<TT, 256>>>(x, b2, out);
}

// round 5
// speedup vs baseline: 5.6606x; 3.6749x over previous
#include <cuda_runtime.h>
#include <cuda_fp16.h>
#include <math.h>
#include <stdint.h>
#include <mma.h>

using namespace nvcuda;

// Problem constants: B=2, S=2048 -> T=4096 tokens, H=1024, E=8, K=2, FF=4096
#define TT   4096
#define HH   1024
#define EE   8
#define FFD  4096
#define RTOT (TT*2)
#define LN_EPS 1e-5f
#define W1N  (EE * HH * FFD)   // 33.5M
#define W2N  (EE * FFD * HH)

// ---------------------------------------------------------------------------
// Scratch
// ---------------------------------------------------------------------------
__device__ __half g_h[RTOT * HH];                    // 16.8 MB
__device__ __half g_act[(long long)RTOT * FFD];      // 67 MB
__device__ float  g_y[RTOT * HH];                    // 33.5 MB
__device__ __half g_W1h[W1N];                        // 67 MB
__device__ __half g_W2h[W2N];                        // 67 MB
__device__ float  g_stat[TT * 2];                    // mu, rsig per token
__device__ int    g_cnt[EE];
__device__ int    g_off[EE + 1];
__device__ int    g_slot_e[RTOT];
__device__ int    g_slot_pos[RTOT];
__device__ int    g_slot_row[RTOT];
__device__ float  g_slot_w[RTOT];
__device__ int    g_row_tok[RTOT];
__device__ int    g_row_e[RTOT];

// ---------------------------------------------------------------------------
// Helpers
// ---------------------------------------------------------------------------
__device__ __forceinline__ uint32_t smem_u32(const void* p) {
    uint32_t a;
    asm("{ .reg .u64 t; cvta.to.shared.u64 t, %1; cvt.u32.u64 %0, t; }" : "=r"(a) : "l"(p));
    return a;
}
#define CP16(dst, src) \
    asm volatile("cp.async.cg.shared.global [%0], [%1], 16;" :: "r"(dst), "l"(src))
#define CP_COMMIT() asm volatile("cp.async.commit_group;" ::: "memory")
#define CP_WAIT0()  asm volatile("cp.async.wait_group 0;" ::: "memory")
#define CP_WAIT1()  asm volatile("cp.async.wait_group 1;" ::: "memory")

// ---------------------------------------------------------------------------
// Weight conversion fp32 -> fp16 (runs every launch; deterministic)
// ---------------------------------------------------------------------------
__global__ void __launch_bounds__(256) k_f2h(const float* __restrict__ src,
                                            __half* __restrict__ dst, int n) {
    int i = (blockIdx.x * 256 + threadIdx.x) * 4;
    for (; i < n; i += gridDim.x * 1024) {
        float4 v = *(const float4*)(src + i);
        __half2 a = __floats2half2_rn(v.x, v.y);
        __half2 b = __floats2half2_rn(v.z, v.w);
        *(uint2*)(dst + i) = make_uint2(*(uint32_t*)&a, *(uint32_t*)&b);
    }
}

// ---------------------------------------------------------------------------
// Kernel 0-4: router / LN / compaction
// ---------------------------------------------------------------------------
__global__ void k_zero() { if (threadIdx.x < EE) g_cnt[threadIdx.x] = 0; }

__global__ void __launch_bounds__(256) k_router_ln(
    const float* __restrict__ x, const float* __restrict__ rW, const float* __restrict__ rb)
{
    __shared__ float xs[HH];
    __shared__ float rs[8], rs2[8];
    __shared__ float lg[EE];

    const int t = blockIdx.x, tid = threadIdx.x;
    const int wid = tid >> 5, lane = tid & 31;
    const float* xr = x + (long long)t * HH;

    float s = 0.f, s2 = 0.f;
    for (int c = tid; c < HH; c += 256) { float v = xr[c]; xs[c] = v; s += v; s2 += v * v; }
    #pragma unroll
    for (int o = 16; o; o >>= 1) {
        s  += __shfl_down_sync(0xFFFFFFFFu, s, o);
        s2 += __shfl_down_sync(0xFFFFFFFFu, s2, o);
    }
    if (lane == 0) { rs[wid] = s; rs2[wid] = s2; }
    __syncthreads();
    if (tid == 0) {
        float S = 0.f, S2 = 0.f;
        #pragma unroll
        for (int i = 0; i < 8; i++) { S += rs[i]; S2 += rs2[i]; }
        float mu = S / (float)HH;
        g_stat[t * 2 + 0] = mu;
        g_stat[t * 2 + 1] = rsqrtf(S2 / (float)HH - mu * mu + LN_EPS);
    }

    float p = 0.f;
    for (int c = lane; c < HH; c += 32) p += xs[c] * rW[c * EE + wid];
    #pragma unroll
    for (int o = 16; o; o >>= 1) p += __shfl_down_sync(0xFFFFFFFFu, p, o);
    if (lane == 0) lg[wid] = p + rb[wid];
    __syncthreads();

    if (tid == 0) {
        int e0 = 0;
        #pragma unroll
        for (int e = 1; e < EE; e++) if (lg[e] > lg[e0]) e0 = e;
        int e1 = (e0 == 0) ? 1 : 0;
        #pragma unroll
        for (int e = 0; e < EE; e++) { if (e == e0) continue; if (lg[e] > lg[e1]) e1 = e; }
        float p1 = expf(lg[e1] - lg[e0]);
        float inv = 1.f / (1.f + p1);
        int   es[2] = { e0, e1 };
        float ws[2] = { inv, p1 * inv };
        #pragma unroll
        for (int k = 0; k < 2; k++) {
            int e = es[k];
            int pos = atomicAdd(&g_cnt[e], 1);
            g_slot_e[t * 2 + k] = e; g_slot_pos[t * 2 + k] = pos; g_slot_w[t * 2 + k] = ws[k];
        }
    }
}

__global__ void k_prefix() {
    if (threadIdx.x == 0) {
        int a = 0;
        #pragma unroll
        for (int e = 0; e < EE; e++) { g_off[e] = a; a += g_cnt[e]; }
        g_off[EE] = a;
    }
}

__global__ void k_build() {
    int i = blockIdx.x * blockDim.x + threadIdx.x;
    if (i >= RTOT) return;
    int e = g_slot_e[i];
    int row = g_off[e] + g_slot_pos[i];
    g_slot_row[i] = row;
    g_row_tok[row] = i >> 1;
    g_row_e[row] = e;
}

// h[row] = ((x[tok]-mu)*rsig * ln_g[e] + ln_b[e]) as fp16
__global__ void __launch_bounds__(256) k_build_h(
    const float* __restrict__ x,
    const float* __restrict__ lng, const float* __restrict__ lnb)
{
    const int row = blockIdx.x;
    const int tok = g_row_tok[row];
    const int e   = g_row_e[row];
    const float mu  = g_stat[tok * 2 + 0];
    const float rsg = g_stat[tok * 2 + 1];
    const float* xr = x + (long long)tok * HH;
    const float* gg = lng + (long long)e * HH;
    const float* bb = lnb + (long long)e * HH;
    __half* o = g_h + (long long)row * HH;
    for (int c = threadIdx.x * 4; c < HH; c += 1024) {
        float4 xv = *(const float4*)(xr + c);
        float4 gv = *(const float4*)(gg + c);
        float4 bv = *(const float4*)(bb + c);
        float h0 = fmaf((xv.x - mu) * rsg, gv.x, bv.x);
        float h1 = fmaf((xv.y - mu) * rsg, gv.y, bv.y);
        float h2 = fmaf((xv.z - mu) * rsg, gv.z, bv.z);
        float h3 = fmaf((xv.w - mu) * rsg, gv.w, bv.w);
        __half2 p0 = __floats2half2_rn(h0, h1);
        __half2 p1 = __floats2half2_rn(h2, h3);
        *(uint2*)(o + c) = make_uint2(*(uint32_t*)&p0, *(uint32_t*)&p1);
    }
}

// ---------------------------------------------------------------------------
// fp16 wmma grouped GEMM: BM=128, BN=128, BK=64, 256 threads (8 warps, 4x2),
// warp tile 32x64 (2x4 m16n16k16 frags, fp32 acc), cp.async double-buffered.
// FIRST: A=g_h[rows,1024] B=g_W1h[e][1024,4096] -> gelu(.+b1) -> g_act (fp16)
// else : A=g_act[rows,4096] B=g_W2h[e][4096,1024] -> g_y (fp32)
// ---------------------------------------------------------------------------
#define A_LDMH 72      // halfs; stride 144B
#define B_LDMH 136     // halfs; stride 272B
#define A_STH (128 * A_LDMH)    // 9216 halfs / stage
#define B_STH (64 * B_LDMH)     // 8704 halfs / stage
#define GEMM_SMEM_BYTES ((2 * A_STH + 2 * B_STH) * 2)   // 71680
#define OUT_LDM 132             // floats; 128*132*4 = 67584 <= 71680

template <bool FIRST>
__global__ void __launch_bounds__(256) k_gemm_h(
    const __half* __restrict__ Wh, const float* __restrict__ bias)
{
    constexpr int KD  = FIRST ? HH : FFD;
    constexpr int ND  = FIRST ? FFD : HH;
    constexpr int NIT = KD / 64;

    const int e    = blockIdx.z;
    const int r0   = g_off[e];
    const int rows = g_off[e + 1] - r0;
    const int row0 = blockIdx.y * 128;
    if (row0 >= rows) return;
    const int n0 = blockIdx.x * 128;

    extern __shared__ __align__(16) char smraw[];
    __half* sm = (__half*)smraw;
    const uint32_t sbase = smem_u32(sm);

    const int tid = threadIdx.x;
    const int w   = tid >> 5;
    const int wm  = w >> 1;     // 0..3
    const int wn  = w & 1;      // 0..1

    const __half* A  = FIRST ? g_h : g_act;
    const __half* Bg = Wh + (size_t)e * KD * ND;

    wmma::fragment<wmma::accumulator, 16, 16, 16, float> acc[2][4];
    #pragma unroll
    for (int i = 0; i < 2; i++)
        #pragma unroll
        for (int j = 0; j < 4; j++) wmma::fill_fragment(acc[i][j], 0.f);

    auto load_stage = [&](int it, int buf) {
        const int k0 = it * 64;
        // A: 128 rows x 64 halfs = 1024 chunks of 8 halfs (16B); 4/thread
        #pragma unroll
        for (int j = 0; j < 4; j++) {
            int idx = tid + 256 * j;
            int r = idx >> 3, kc = (idx & 7) * 8;
            int arow = row0 + r; if (arow >= rows) arow = rows - 1;
            const __half* src = A + (size_t)(r0 + arow) * KD + k0 + kc;
            uint32_t dst = sbase + (uint32_t)(buf * A_STH + r * A_LDMH + kc) * 2u;
            CP16(dst, src);
        }
        // B: 64 k x 128 n = 1024 chunks of 8 halfs; 4/thread
        #pragma unroll
        for (int j = 0; j < 4; j++) {
            int idx = tid + 256 * j;
            int kk = idx >> 4, nc = (idx & 15) * 8;
            const __half* src = Bg + (size_t)(k0 + kk) * ND + n0 + nc;
            uint32_t dst = sbase + (uint32_t)(2 * A_STH + buf * B_STH + kk * B_LDMH + nc) * 2u;
            CP16(dst, src);
        }
        CP_COMMIT();
    };

    load_stage(0, 0);

    for (int it = 0; it < NIT; ++it) {
        if (it + 1 < NIT) { load_stage(it + 1, (it + 1) & 1); CP_WAIT1(); }
        else              { CP_WAIT0(); }
        __syncthreads();

        const __half* pA = sm + (it & 1) * A_STH;
        const __half* pB = sm + 2 * A_STH + (it & 1) * B_STH;

        #pragma unroll
        for (int ks = 0; ks < 4; ks++) {
            wmma::fragment<wmma::matrix_a, 16, 16, 16, __half, wmma::row_major> af[2];
            wmma::fragment<wmma::matrix_b, 16, 16, 16, __half, wmma::row_major> bf[4];
            #pragma unroll
            for (int i = 0; i < 2; i++)
                wmma::load_matrix_sync(af[i], pA + (wm * 32 + i * 16) * A_LDMH + ks * 16, A_LDMH);
            #pragma unroll
            for (int j = 0; j < 4; j++)
                wmma::load_matrix_sync(bf[j], pB + (ks * 16) * B_LDMH + wn * 64 + j * 16, B_LDMH);
            #pragma unroll
            for (int i = 0; i < 2; i++)
                #pragma unroll
                for (int j = 0; j < 4; j++)
                    wmma::mma_sync(acc[i][j], af[i], bf[j], acc[i][j]);
        }
        __syncthreads();
    }

    // Epilogue via smem fp32 (guarded; partial m-tiles stay inside segment)
    float* smf = (float*)smraw;
    #pragma unroll
    for (int i = 0; i < 2; i++)
        #pragma unroll
        for (int j = 0; j < 4; j++)
            wmma::store_matrix_sync(
                smf + (size_t)(wm * 32 + i * 16) * OUT_LDM + wn * 64 + j * 16,
                acc[i][j], OUT_LDM, wmma::mem_row_major);
    __syncthreads();

    const int col = (tid & 31) * 4;
    const float* brow = FIRST ? (bias + (size_t)e * ND + n0) : (const float*)0;
    #pragma unroll
    for (int rr = 0; rr < 16; rr++) {
        int r = (tid >> 5) + rr * 8;
        int m = row0 + r;
        if (m < rows) {
            const float* so = smf + (size_t)r * OUT_LDM + col;
            float v0 = so[0], v1 = so[1], v2 = so[2], v3 = so[3];
            if (FIRST) {
                float4 bv = *(const float4*)(brow + col);
                v0 += bv.x; v1 += bv.y; v2 += bv.z; v3 += bv.w;
                v0 = 0.5f * v0 * (1.0f + erff(v0 * 0.70710678118654752f));
                v1 = 0.5f * v1 * (1.0f + erff(v1 * 0.70710678118654752f));
                v2 = 0.5f * v2 * (1.0f + erff(v2 * 0.70710678118654752f));
                v3 = 0.5f * v3 * (1.0f + erff(v3 * 0.70710678118654752f));
                __half2 p0 = __floats2half2_rn(v0, v1);
                __half2 p1 = __floats2half2_rn(v2, v3);
                *(uint2*)(g_act + (size_t)(r0 + m) * ND + n0 + col) =
                    make_uint2(*(uint32_t*)&p0, *(uint32_t*)&p1);
            } else {
                *(float4*)(g_y + (size_t)(r0 + m) * ND + n0 + col) =
                    make_float4(v0, v1, v2, v3);
            }
        }
    }
}

// ---------------------------------------------------------------------------
// Combine: out = x + w0*(y0 + b2[e0]) + w1*(y1 + b2[e1])
// ---------------------------------------------------------------------------
__global__ void __launch_bounds__(256) k_combine(
    const float* __restrict__ x, const float* __restrict__ b2, float* __restrict__ out)
{
    const int t = blockIdx.x;
    const int r0 = g_slot_row[t * 2 + 0], r1 = g_slot_row[t * 2 + 1];
    const int e0 = g_slot_e[t * 2 + 0],  e1 = g_slot_e[t * 2 + 1];
    const float w0 = g_slot_w[t * 2 + 0], w1 = g_slot_w[t * 2 + 1];
    const float* y0 = g_y + (long long)r0 * HH;
    const float* y1 = g_y + (long long)r1 * HH;
    const float* bb0 = b2 + (long long)e0 * HH;
    const float* bb1 = b2 + (long long)e1 * HH;
    const float* xr = x + (long long)t * HH;
    float* o = out + (long long)t * HH;
    for (int c = threadIdx.x; c < HH; c += 256)
        o[c] = xr[c] + w0 * (y0[c] + bb0[c]) + w1 * (y1[c] + bb1[c]);
}

// ---------------------------------------------------------------------------
// Launch
// ---------------------------------------------------------------------------
extern "C" void kernel_launch(void* const* d_in, const int* in_sizes, int n_in,
                              void* d_out, int out_size)
{
    const float* x   = (const float*)d_in[0];
    const float* rW  = (const float*)d_in[1];
    const float* rb  = (const float*)d_in[2];
    const float* lng = (const float*)d_in[3];
    const float* lnb = (const float*)d_in[4];
    const float* W1  = (const float*)d_in[5];
    const float* b1  = (const float*)d_in[6];
    const float* W2  = (const float*)d_in[7];
    const float* b2  = (const float*)d_in[8];
    float* out = (float*)d_out;

    cudaFuncSetAttribute(k_gemm_h<true>,  cudaFuncAttributeMaxDynamicSharedMemorySize, GEMM_SMEM_BYTES);
    cudaFuncSetAttribute(k_gemm_h<false>, cudaFuncAttributeMaxDynamicSharedMemorySize, GEMM_SMEM_BYTES);

    __half* w1h; cudaGetSymbolAddress((void**)&w1h, g_W1h);
    __half* w2h; cudaGetSymbolAddress((void**)&w2h, g_W2h);

    k_f2h<<<2048, 256>>>(W1, w1h, W1N);
    k_f2h<<<2048, 256>>>(W2, w2h, W2N);

    k_zero<<<1, 32>>>();
    k_router_ln<<<TT, 256>>>(x, rW, rb);
    k_prefix<<<1, 32>>>();
    k_build<<<RTOT / 256, 256>>>();
    k_build_h<<<RTOT, 256>>>(x, lng, lnb);

    dim3 g1(FFD / 128, RTOT / 128, EE);   // 32 x 64 x 8 (most m-tiles exit early)
    k_gemm_h<true><<<g1, 256, GEMM_SMEM_BYTES>>>(w1h, b1);

    dim3 g2(HH / 128, RTOT / 128, EE);    // 8 x 64 x 8
    k_gemm_h<false><<<g2, 256, GEMM_SMEM_BYTES>>>(w2h, nullptr);

    k_combine<<<TT, 256>>>(x, b2, out);
}